// round 6
// baseline (speedup 1.0000x reference)
#include <cuda_runtime.h>
#include <cuda_fp16.h>

#define BATCH 8
#define SEQ   4096
#define HID   1024
#define K1N   33        // Hermitian: only k1 = 0..32 of 64 needed
#define TILE_H 16       // h-columns per block
// Padded k1-row stride in half2 words: 64*16 + 16 -> consecutive k1 rows are
// offset by 16 banks, making phase-2's 2-k1-per-warp LDS conflict-free.
#define Y_STRIDE (64 * TILE_H + 16)

// smem layout: sY (half2[33][Y_STRIDE]) then sTW (float2[64*33])
#define SY_BYTES  (K1N * Y_STRIDE * 4)
#define STW_BYTES (64 * K1N * 8)
#define SMEM_BYTES (SY_BYTES + STW_BYTES)   // 137280 + 16896 = 154176 B

__device__ __forceinline__ constexpr int rev6(int x) {
    return ((x & 1) << 5) | ((x & 2) << 3) | ((x & 4) << 1) |
           ((x & 8) >> 1) | ((x & 16) >> 3) | ((x & 32) >> 5);
}

// W_64^j literal tables (compile-time indexed -> FFMA immediates)
__device__ __forceinline__ float tw64_re(int j) {
    constexpr float c[32] = {
        1.00000000000f, 0.99518472667f, 0.98078528040f, 0.95694033573f,
        0.92387953251f, 0.88192126435f, 0.83146961230f, 0.77301045336f,
        0.70710678119f, 0.63439328416f, 0.55557023302f, 0.47139673683f,
        0.38268343236f, 0.29028467725f, 0.19509032202f, 0.09801714033f,
        0.00000000000f,-0.09801714033f,-0.19509032202f,-0.29028467725f,
       -0.38268343236f,-0.47139673683f,-0.55557023302f,-0.63439328416f,
       -0.70710678119f,-0.77301045336f,-0.83146961230f,-0.88192126435f,
       -0.92387953251f,-0.95694033573f,-0.98078528040f,-0.99518472667f };
    return c[j];
}
__device__ __forceinline__ float tw64_im(int j) {
    constexpr float s[32] = {
       -0.00000000000f,-0.09801714033f,-0.19509032202f,-0.29028467725f,
       -0.38268343236f,-0.47139673683f,-0.55557023302f,-0.63439328416f,
       -0.70710678119f,-0.77301045336f,-0.83146961230f,-0.88192126435f,
       -0.92387953251f,-0.95694033573f,-0.98078528040f,-0.99518472667f,
       -1.00000000000f,-0.99518472667f,-0.98078528040f,-0.95694033573f,
       -0.92387953251f,-0.88192126435f,-0.83146961230f,-0.77301045336f,
       -0.70710678119f,-0.63439328416f,-0.55557023302f,-0.47139673683f,
       -0.38268343236f,-0.29028467725f,-0.19509032202f,-0.09801714033f };
    return s[j];
}

// In-register 64-point DIF radix-2 FFT (bit-reversed output: X[k]=re[rev6(k)]).
__device__ __forceinline__ void fft64(float (&re)[64], float (&im)[64]) {
#pragma unroll
    for (int stage = 0; stage < 6; stage++) {
        const int s = 32 >> stage;
#pragma unroll
        for (int j = 0; j < 64; j += 2 * s) {
#pragma unroll
            for (int t = 0; t < s; t++) {
                const int a = j + t, b = a + s;
                float ar = re[a], ai = im[a];
                float br = re[b], bi = im[b];
                re[a] = ar + br;  im[a] = ai + bi;
                float dr = ar - br, di = ai - bi;
                const int ti = t << stage;
                float wr = tw64_re(ti), wi = tw64_im(ti);
                re[b] = dr * wr - di * wi;
                im[b] = dr * wi + di * wr;
            }
        }
    }
}

// Fused FNet FFT: per block (b, 16 h-columns), full 4096-pt real FFT along seq.
// Phase 1: FFT64 over n1 (seq = 64*n1 + n2) + twiddle W_4096^{n2*k1}, k1<=32,
//          half2 result in smem.  Phase 2: FFT64 over n2, write Re + mirror.
__global__ void __launch_bounds__(256, 1)
fft_fused(const float* __restrict__ x, float* __restrict__ out) {
    extern __shared__ unsigned char smem_raw[];
    __half2* sY  = (__half2*)smem_raw;                    // [K1N][Y_STRIDE]
    float2*  sTW = (float2*)(smem_raw + SY_BYTES);        // [64][K1N]

    const int tid = threadIdx.x;
    const int hl  = tid & 15;
    const int r   = tid >> 4;        // 0..15
    const int h   = blockIdx.x * TILE_H + hl;
    const int b   = blockIdx.y;

    // One-time exact twiddle table: W_4096^{n2*k1}, n2=0..63, k1=0..32.
#pragma unroll 1
    for (int idx = tid; idx < 64 * K1N; idx += 256) {
        int n2 = idx / K1N, k1 = idx - n2 * K1N;
        float s, c;
        sincospif(-(float)(n2 * k1) / 2048.0f, &s, &c);
        sTW[idx] = make_float2(c, s);
    }
    __syncthreads();

    // ---- Phase 1: 4 iterations cover n2 = 0..63 (16 rows at a time) ----
#pragma unroll 1
    for (int i = 0; i < 4; i++) {
        const int n2 = 16 * i + r;
        const float* xp = x + ((size_t)(b * SEQ + n2)) * HID + h;
        float re[64], im[64];
#pragma unroll
        for (int n1 = 0; n1 < 64; n1++) {
            re[n1] = __ldcs(xp + (size_t)n1 * 64 * HID);  // streaming read
            im[n1] = 0.0f;
        }
        fft64(re, im);

        __half2* yp = sY + n2 * TILE_H + hl;
#pragma unroll
        for (int k1 = 0; k1 < K1N; k1++) {
            float2 w = sTW[n2 * K1N + k1];
            float vr = re[rev6(k1)], vi = im[rev6(k1)];
            yp[k1 * Y_STRIDE] = __floats2half2_rn(vr * w.x - vi * w.y,
                                                  vr * w.y + vi * w.x);
        }
    }
    __syncthreads();

    // ---- Phase 2: k1 = 16*j + r; j=0,1 full, j=2 only r==0 (k1=32) ----
    float* op = out + (size_t)b * SEQ * HID + h;
    const float scale = 1.0f / 64.0f;   // ortho norm 1/sqrt(4096)
#pragma unroll 1
    for (int j = 0; j < 3; j++) {
        const int k1 = 16 * j + r;
        if (k1 > 32) break;             // j=2: warps 1..7 exit uniformly
        const __half2* yp = sY + k1 * Y_STRIDE + hl;
        float re[64], im[64];
#pragma unroll
        for (int n2 = 0; n2 < 64; n2++) {
            float2 v = __half22float2(yp[n2 * TILE_H]);
            re[n2] = v.x; im[n2] = v.y;
        }
        fft64(re, im);

        const bool mirror = (k1 >= 1 && k1 <= 31);
#pragma unroll
        for (int k2 = 0; k2 < 64; k2++) {
            const float val = re[rev6(k2)] * scale;
            __stcs(op + (size_t)(k1 + 64 * k2) * HID, val);
            // Re X[4096-m] = Re X[m]:  (64-k1) + 64*(63-k2)  <->  k1 + 64*k2
            if (mirror)
                __stcs(op + (size_t)((64 - k1) + 64 * (63 - k2)) * HID, val);
        }
    }
}

extern "C" void kernel_launch(void* const* d_in, const int* in_sizes, int n_in,
                              void* d_out, int out_size) {
    const float* x = (const float*)d_in[0];
    float* out = (float*)d_out;

    cudaFuncSetAttribute(fft_fused,
                         cudaFuncAttributeMaxDynamicSharedMemorySize, SMEM_BYTES);
    fft_fused<<<dim3(HID / TILE_H, BATCH), 256, SMEM_BYTES>>>(x, out);
}

// round 7
// speedup vs baseline: 1.0882x; 1.0882x over previous
#include <cuda_runtime.h>
#include <cuda_fp16.h>

#define BATCH 8
#define SEQ   4096
#define HID   1024
#define K1N   33        // Hermitian: store only k1 = 0..32 of 64
#define NCHUNK 4        // pipeline chunks over batch
#define BPC   (BATCH / NCHUNK)

// Scratch: Y[b][n2][k1(0..32)][h] as half2(re,im): 69 MB total; per-chunk
// working set is 17 MB -> fully L2-resident between P1(c) and P2(c).
__device__ __half2 g_scratch[(size_t)BATCH * 64 * K1N * HID];

// Bit-reverse of 6-bit value (compile-time in unrolled loops)
__device__ __forceinline__ constexpr int rev6(int x) {
    return ((x & 1) << 5) | ((x & 2) << 3) | ((x & 4) << 1) |
           ((x & 8) >> 1) | ((x & 16) >> 3) | ((x & 32) >> 5);
}

// W_64^j, j in [0,32). Literal constants -> FFMA immediates.
__device__ __forceinline__ float tw64_re(int j) {
    constexpr float c[32] = {
        1.00000000000f, 0.99518472667f, 0.98078528040f, 0.95694033573f,
        0.92387953251f, 0.88192126435f, 0.83146961230f, 0.77301045336f,
        0.70710678119f, 0.63439328416f, 0.55557023302f, 0.47139673683f,
        0.38268343236f, 0.29028467725f, 0.19509032202f, 0.09801714033f,
        0.00000000000f,-0.09801714033f,-0.19509032202f,-0.29028467725f,
       -0.38268343236f,-0.47139673683f,-0.55557023302f,-0.63439328416f,
       -0.70710678119f,-0.77301045336f,-0.83146961230f,-0.88192126435f,
       -0.92387953251f,-0.95694033573f,-0.98078528040f,-0.99518472667f };
    return c[j];
}
__device__ __forceinline__ float tw64_im(int j) {
    constexpr float s[32] = {
       -0.00000000000f,-0.09801714033f,-0.19509032202f,-0.29028467725f,
       -0.38268343236f,-0.47139673683f,-0.55557023302f,-0.63439328416f,
       -0.70710678119f,-0.77301045336f,-0.83146961230f,-0.88192126435f,
       -0.92387953251f,-0.95694033573f,-0.98078528040f,-0.99518472667f,
       -1.00000000000f,-0.99518472667f,-0.98078528040f,-0.95694033573f,
       -0.92387953251f,-0.88192126435f,-0.83146961230f,-0.77301045336f,
       -0.70710678119f,-0.63439328416f,-0.55557023302f,-0.47139673683f,
       -0.38268343236f,-0.29028467725f,-0.19509032202f,-0.09801714033f };
    return s[j];
}

// In-register 64-point DIF radix-2 FFT. Output bit-reversed:
// X[k] = re[rev6(k)], im[rev6(k)].
__device__ __forceinline__ void fft64(float (&re)[64], float (&im)[64]) {
#pragma unroll
    for (int stage = 0; stage < 6; stage++) {
        const int s = 32 >> stage;
#pragma unroll
        for (int j = 0; j < 64; j += 2 * s) {
#pragma unroll
            for (int t = 0; t < s; t++) {
                const int a = j + t;
                const int b = a + s;
                float ar = re[a], ai = im[a];
                float br = re[b], bi = im[b];
                re[a] = ar + br;
                im[a] = ai + bi;
                float dr = ar - br, di = ai - bi;
                const int ti = t << stage;
                float wr = tw64_re(ti), wi = tw64_im(ti);
                re[b] = dr * wr - di * wi;
                im[b] = dr * wi + di * wr;
            }
        }
    }
}

// Pass 1 (identical to R3 apart from batch offset): per (b, n2, h):
// A[k1] = FFT64 over n1; Y = A[k1] * W_4096^{n2*k1}, fp16, k1 = 0..32.
__global__ void __launch_bounds__(128) fft_pass1(const float* __restrict__ x,
                                                 int b0) {
    const int h  = blockIdx.x * 128 + threadIdx.x;  // HID/128 = 8
    const int n2 = blockIdx.y;                      // 64
    const int b  = b0 + blockIdx.z;

    const float* xp = x + ((size_t)b * SEQ + n2) * HID + h;
    float re[64], im[64];
#pragma unroll
    for (int n1 = 0; n1 < 64; n1++) {
        re[n1] = __ldcs(xp + (size_t)n1 * 64 * HID);  // streaming read
        im[n1] = 0.0f;
    }
    fft64(re, im);

    // base twiddle W_4096^{n2} = exp(-i*pi*n2/2048)
    float bs, bc;
    sincospif(-(float)n2 / 2048.0f, &bs, &bc);

    __half2* yp = g_scratch + ((size_t)(b * 64 + n2) * K1N) * HID + h;
    float wr = 1.0f, wi = 0.0f;  // W^0
#pragma unroll
    for (int k1 = 0; k1 < K1N; k1++) {
        float vr = re[rev6(k1)], vi = im[rev6(k1)];
        yp[(size_t)k1 * HID] = __floats2half2_rn(vr * wr - vi * wi,
                                                 vr * wi + vi * wr);
        float nwr = wr * bc - wi * bs;
        float nwi = wr * bs + wi * bc;
        wr = nwr; wi = nwi;
    }
}

// Pass 2 (identical to R3 apart from batch offset): per (b, k1, h):
// X[k1 + 64*k2] = FFT64 over n2 of Y[n2][k1]; write Re*(1/64) + mirror row.
__global__ void __launch_bounds__(128) fft_pass2(float* __restrict__ out,
                                                 int b0) {
    const int h  = blockIdx.x * 128 + threadIdx.x;
    const int k1 = blockIdx.y;                      // 0..32
    const int b  = b0 + blockIdx.z;

    const __half2* yp = g_scratch + ((size_t)(b * 64) * K1N + k1) * HID + h;
    float re[64], im[64];
#pragma unroll
    for (int n2 = 0; n2 < 64; n2++) {
        float2 v = __half22float2(yp[(size_t)n2 * K1N * HID]);  // L2 hit
        re[n2] = v.x;
        im[n2] = v.y;
    }
    fft64(re, im);

    float* op = out + ((size_t)b * SEQ) * HID + h;
    const float scale = 1.0f / 64.0f;  // ortho norm 1/sqrt(4096)
#pragma unroll
    for (int k2 = 0; k2 < 64; k2++) {
        __stcs(op + (size_t)(k1 + 64 * k2) * HID, re[rev6(k2)] * scale);
    }
    if (k1 >= 1 && k1 <= 31) {
        const int k1m = 64 - k1;
#pragma unroll
        for (int k2 = 0; k2 < 64; k2++) {
            __stcs(op + (size_t)(k1m + 64 * k2) * HID, re[rev6(63 - k2)] * scale);
        }
    }
}

extern "C" void kernel_launch(void* const* d_in, const int* in_sizes, int n_in,
                              void* d_out, int out_size) {
    const float* x = (const float*)d_in[0];
    float* out = (float*)d_out;

    // One-time setup on the first (correctness) call; nothing is created
    // during graph capture. No device memory is allocated.
    static cudaStream_t s1 = nullptr;
    static cudaEvent_t evP1[NCHUNK];
    static cudaEvent_t evDone = nullptr;
    if (s1 == nullptr) {
        cudaStreamCreateWithFlags(&s1, cudaStreamNonBlocking);
        for (int c = 0; c < NCHUNK; c++)
            cudaEventCreateWithFlags(&evP1[c], cudaEventDisableTiming);
        cudaEventCreateWithFlags(&evDone, cudaEventDisableTiming);
    }

    // Pipeline: P1(c) on the launch stream; P2(c) on s1 after P1(c),
    // overlapping P2(c)'s DRAM writes with P1(c+1)'s DRAM reads.
    for (int c = 0; c < NCHUNK; c++) {
        fft_pass1<<<dim3(HID / 128, 64, BPC), 128>>>(x, c * BPC);
        cudaEventRecord(evP1[c], 0);
        cudaStreamWaitEvent(s1, evP1[c], 0);
        fft_pass2<<<dim3(HID / 128, K1N, BPC), 128, 0, s1>>>(out, c * BPC);
    }
    // Join the side stream back so the graph's leaf is on the launch stream.
    cudaEventRecord(evDone, s1);
    cudaStreamWaitEvent(0, evDone, 0);
}

// round 10
// speedup vs baseline: 1.2474x; 1.1462x over previous
#include <cuda_runtime.h>
#include <cuda_fp16.h>

#define BATCH 8
#define SEQ   4096
#define HID   1024
#define K1N   33   // Hermitian: store only k1 = 0..32 of 64

// Scratch: Y[b][n2][k1(0..32)][h] as half2(re,im): 69 MB. Fits in 126 MB L2;
// input/output use streaming (.cs) so scratch stays resident pass1 -> pass2.
__device__ __half2 g_scratch[(size_t)BATCH * 64 * K1N * HID];

// Bit-reverse of 6-bit value (compile-time in unrolled loops)
__device__ __forceinline__ constexpr int rev6(int x) {
    return ((x & 1) << 5) | ((x & 2) << 3) | ((x & 4) << 1) |
           ((x & 8) >> 1) | ((x & 16) >> 3) | ((x & 32) >> 5);
}

// W_64^j, j in [0,32). Literal constants -> FFMA immediates.
__device__ __forceinline__ float tw64_re(int j) {
    constexpr float c[32] = {
        1.00000000000f, 0.99518472667f, 0.98078528040f, 0.95694033573f,
        0.92387953251f, 0.88192126435f, 0.83146961230f, 0.77301045336f,
        0.70710678119f, 0.63439328416f, 0.55557023302f, 0.47139673683f,
        0.38268343236f, 0.29028467725f, 0.19509032202f, 0.09801714033f,
        0.00000000000f,-0.09801714033f,-0.19509032202f,-0.29028467725f,
       -0.38268343236f,-0.47139673683f,-0.55557023302f,-0.63439328416f,
       -0.70710678119f,-0.77301045336f,-0.83146961230f,-0.88192126435f,
       -0.92387953251f,-0.95694033573f,-0.98078528040f,-0.99518472667f };
    return c[j];
}
__device__ __forceinline__ float tw64_im(int j) {
    constexpr float s[32] = {
       -0.00000000000f,-0.09801714033f,-0.19509032202f,-0.29028467725f,
       -0.38268343236f,-0.47139673683f,-0.55557023302f,-0.63439328416f,
       -0.70710678119f,-0.77301045336f,-0.83146961230f,-0.88192126435f,
       -0.92387953251f,-0.95694033573f,-0.98078528040f,-0.99518472667f,
       -1.00000000000f,-0.99518472667f,-0.98078528040f,-0.95694033573f,
       -0.92387953251f,-0.88192126435f,-0.83146961230f,-0.77301045336f,
       -0.70710678119f,-0.63439328416f,-0.55557023302f,-0.47139673683f,
       -0.38268343236f,-0.29028467725f,-0.19509032202f,-0.09801714033f };
    return s[j];
}

// In-register 64-point DIF radix-2 FFT. Output bit-reversed:
// X[k] = re[rev6(k)], im[rev6(k)].
__device__ __forceinline__ void fft64(float (&re)[64], float (&im)[64]) {
#pragma unroll
    for (int stage = 0; stage < 6; stage++) {
        const int s = 32 >> stage;
#pragma unroll
        for (int j = 0; j < 64; j += 2 * s) {
#pragma unroll
            for (int t = 0; t < s; t++) {
                const int a = j + t;
                const int b = a + s;
                float ar = re[a], ai = im[a];
                float br = re[b], bi = im[b];
                re[a] = ar + br;
                im[a] = ai + bi;
                float dr = ar - br, di = ai - bi;
                const int ti = t << stage;
                float wr = tw64_re(ti), wi = tw64_im(ti);
                re[b] = dr * wr - di * wi;
                im[b] = dr * wi + di * wr;
            }
        }
    }
}

// Pass 1 with two-for-one real FFT: each thread handles h = 2*t and h+1.
// z[n1] = x[h] + i*x[h+1]; one FFT64 over n1; Hermitian split recovers
// A_h[k1], A_{h+1}[k1]; twiddle by W_4096^{n2*k1}; store both half2 as u64.
__global__ void __launch_bounds__(128) fft_pass1(const float* __restrict__ x) {
    const int hp = blockIdx.x * 128 + threadIdx.x;  // h-pair index, HID/2 = 512
    const int h  = 2 * hp;
    const int n2 = blockIdx.y;                      // 64
    const int b  = blockIdx.z;                      // 8

    const float2* xp = (const float2*)(x + ((size_t)b * SEQ + n2) * HID + h);
    float re[64], im[64];
#pragma unroll
    for (int n1 = 0; n1 < 64; n1++) {
        float2 v = __ldcs(xp + (size_t)n1 * 32 * HID);  // 64*HID floats / 2
        re[n1] = v.x;   // x[h]
        im[n1] = v.y;   // x[h+1]
    }
    fft64(re, im);

    // base twiddle W_4096^{n2} = exp(-i*pi*n2/2048)
    float bs, bc;
    sincospif(-(float)n2 / 2048.0f, &bs, &bc);

    // Store two adjacent half2 (h, h+1) as one 8-byte value.
    uint2* yp = (uint2*)(g_scratch + ((size_t)(b * 64 + n2) * K1N) * HID + h);
    float wr = 1.0f, wi = 0.0f;  // W^0
#pragma unroll
    for (int k1 = 0; k1 < K1N; k1++) {
        // Z[k1] and Z[(64-k1) & 63] from bit-reversed registers
        const int km = (64 - k1) & 63;
        float zr = re[rev6(k1)], zi = im[rev6(k1)];
        float mr = re[rev6(km)], mi = im[rev6(km)];
        // A_h = 0.5*(Z + conj(Zm));  A_{h+1} = -0.5i*(Z - conj(Zm))
        float ar = 0.5f * (zr + mr);
        float ai = 0.5f * (zi - mi);
        float br2 = 0.5f * (zi + mi);
        float bi2 = 0.5f * (mr - zr);
        // twiddle both by w
        __half2 ya = __floats2half2_rn(ar * wr - ai * wi, ar * wi + ai * wr);
        __half2 yb = __floats2half2_rn(br2 * wr - bi2 * wi, br2 * wi + bi2 * wr);
        uint2 packed;
        packed.x = reinterpret_cast<unsigned int&>(ya);
        packed.y = reinterpret_cast<unsigned int&>(yb);
        yp[(size_t)k1 * (HID / 2)] = packed;
        // w *= base
        float nwr = wr * bc - wi * bs;
        float nwi = wr * bs + wi * bc;
        wr = nwr; wi = nwi;
    }
}

// Pass 2 (identical to R3): per (b, k1 in 0..32, h): FFT64 over n2 of Y[n2][k1];
// write Re*(1/64) for row k1 and Hermitian mirror row 64-k1.
__global__ void __launch_bounds__(128) fft_pass2(float* __restrict__ out) {
    const int h  = blockIdx.x * 128 + threadIdx.x;
    const int k1 = blockIdx.y;                      // 0..32
    const int b  = blockIdx.z;

    const __half2* yp = g_scratch + ((size_t)(b * 64) * K1N + k1) * HID + h;
    float re[64], im[64];
#pragma unroll
    for (int n2 = 0; n2 < 64; n2++) {
        float2 v = __half22float2(yp[(size_t)n2 * K1N * HID]);  // L2 hit
        re[n2] = v.x;
        im[n2] = v.y;
    }
    fft64(re, im);

    float* op = out + ((size_t)b * SEQ) * HID + h;
    const float scale = 1.0f / 64.0f;  // ortho norm 1/sqrt(4096)
#pragma unroll
    for (int k2 = 0; k2 < 64; k2++) {
        __stcs(op + (size_t)(k1 + 64 * k2) * HID, re[rev6(k2)] * scale);
    }
    if (k1 >= 1 && k1 <= 31) {
        const int k1m = 64 - k1;
#pragma unroll
        for (int k2 = 0; k2 < 64; k2++) {
            __stcs(op + (size_t)(k1m + 64 * k2) * HID, re[rev6(63 - k2)] * scale);
        }
    }
}

extern "C" void kernel_launch(void* const* d_in, const int* in_sizes, int n_in,
                              void* d_out, int out_size) {
    const float* x = (const float*)d_in[0];
    float* out = (float*)d_out;

    fft_pass1<<<dim3(HID / 2 / 128, 64, BATCH), 128>>>(x);
    fft_pass2<<<dim3(HID / 128, K1N, BATCH), 128>>>(out);
}